// round 6
// baseline (speedup 1.0000x reference)
#include <cuda_runtime.h>
#include <cstdint>

// Problem constants (fixed by the dataset)
#define BATCH   16
#define C_IN    64
#define HH      32
#define WW      32
#define C_OUT   128
#define PH      34              // padded plane height (1 + 32 + 1)
#define PW      40              // padded plane width: 4 left + 32 + 4 right
#define PLANE   (PH*PW)         // 1360 floats (even)
#define PSZ2    2728            // storage per plane: v0 [0,1360) + v1 [1361,2721) + pad (16B mult)
#define BUF     (2*PSZ2)        // one batch = 2 planes (both copies) = 5456 floats
#define NB      2               // batches per block

typedef unsigned long long ull;

// 16B async copy global->shared (LDGSTS.128)
__device__ __forceinline__ void cp16(float* dst_smem, const float* src) {
    uint32_t d = (uint32_t)__cvta_generic_to_shared(dst_smem);
    asm volatile("cp.async.cg.shared.global [%0], [%1], 16;\n" :: "r"(d), "l"(src));
}
// 4B async copy global->shared (for the shifted v1 copy; 4B-aligned dst)
__device__ __forceinline__ void cp4(float* dst_smem, const float* src) {
    uint32_t d = (uint32_t)__cvta_generic_to_shared(dst_smem);
    asm volatile("cp.async.ca.shared.global [%0], [%1], 4;\n" :: "r"(d), "l"(src));
}

// packed f32x2 FMA (SASS FFMA2) — per-lane IEEE fp32 fma
__device__ __forceinline__ ull ffma2(ull a, ull b, ull c) {
    ull d;
    asm("fma.rn.f32x2 %0, %1, %2, %3;" : "=l"(d) : "l"(a), "l"(b), "l"(c));
    return d;
}
// broadcast a scalar into both lanes of an f32x2
__device__ __forceinline__ ull pack2(float v) {
    ull d; uint32_t u = __float_as_uint(v);
    asm("mov.b64 %0, {%1, %1};" : "=l"(d) : "r"(u));
    return d;
}
// aligned 8-byte shared load with literal byte offset
template <int IMM>
__device__ __forceinline__ ull lds64(uint32_t addr) {
    ull v;
    asm volatile("ld.shared.b64 %0, [%1 + %2];" : "=l"(v) : "r"(addr), "n"(IMM));
    return v;
}

// packed gate: c0 + ca*a + cb*b + cab*a*b = fma(fma(cab,b,ca), a, fma(cb,b,c0))
__device__ __forceinline__ ull gate2(const ull K[4], ull a, ull b) {
    return ffma2(ffma2(K[3], b, K[1]), a, ffma2(K[2], b, K[0]));
}

// ---------------------------------------------------------------------------
// One block per (oc, batch-pair). Each plane is staged twice: v0 (aligned,
// cp.async 16B) and v1 (shifted by one word so odd elements sit at even
// addresses, cp.async 4B). Every leaf then reads parity-aligned LDS.64 pairs;
// all tree math is packed f32x2 (FFMA2). Hot loop per pixel-pair:
// 8 LDS.64 + 21 FFMA2 + 1 STG.64.
// ---------------------------------------------------------------------------
__global__ void __launch_bounds__(256, 4)
tree_kernel(const float* __restrict__ x,
            const float* __restrict__ w,
            const int*   __restrict__ leaf_idx,
            float*       __restrict__ out)
{
    __shared__ __align__(16) float sm[NB * BUF];   // 43648 B
    __shared__ float s_coef[16];                   // 4 gates x {c0,ca,cb,cab}
    __shared__ int   s_off[8];                     // leaf word offsets (parity-resolved)

    const int blk = blockIdx.x;          // 0..1023
    const int oc  = blk & (C_OUT - 1);
    const int bg  = blk >> 7;            // 0..7 -> batches 2*bg, 2*bg+1
    const int tid = threadIdx.x;

    // --- source channels (broadcast loads; const-div -> mul-hi) ----------
    const int chA = __ldg(&leaf_idx[oc * 8 + 0]) / 9;
    const int chB = __ldg(&leaf_idx[oc * 8 + 4]) / 9;

    // --- issue async stages for both batches (one commit group per batch) --
    #pragma unroll
    for (int u = 0; u < NB; u++) {
        const float* xb = x + ((size_t)(bg * NB + u) * C_IN) * (HH * WW);
        // v0: 2 planes x 256 float4 -> 2 cp16 per thread
        #pragma unroll
        for (int i = 0; i < 2; i++) {
            int t  = tid + i * 256;      // 0..511
            int p  = t >> 8;             // plane select
            int j  = t & 255;            // r*8 + c4
            int r  = j >> 3;
            int c4 = j & 7;
            const float* src = xb + (p ? chB : chA) * (HH * WW) + j * 4;
            float* dst = sm + u * BUF + p * PSZ2 + (r + 1) * PW + 4 + c4 * 4;
            cp16(dst, src);
        }
        // v1 (shifted copy): 2 planes x 1024 words -> 8 cp4 per thread
        #pragma unroll
        for (int i = 0; i < 8; i++) {
            int t = tid + i * 256;       // 0..2047
            int p = t >> 10;
            int j = t & 1023;            // r*32 + c
            int r = j >> 5;
            int c = j & 31;
            const float* src = xb + (p ? chB : chA) * (HH * WW) + j;
            float* dst = sm + u * BUF + p * PSZ2 + 1361 + (r + 1) * PW + 4 + c;
            cp4(dst, src);
        }
        asm volatile("cp.async.commit_group;\n");
    }

    // --- zero the border words of all 4 plane-buffers, both copies -------
    // v0: float4 slots (cols 0-3 / 36-39 all rows; rows 0 & 33 cols 4-35)
    {
        float4 z4 = make_float4(0.f, 0.f, 0.f, 0.f);
        float4* smv = (float4*)sm;
        #pragma unroll
        for (int i = 0; i < 2; i++) {
            int t = tid + i * 256;       // 0..511 = 4 plane-buffers x 128 slots
            int q = t >> 7;              // plane-buffer 0..3
            int k = t & 127;
            if (k < 84) {
                int f4;
                if (k < 68)      f4 = (k >> 1) * 10 + ((k & 1) ? 9 : 0);
                else if (k < 76) f4 = k - 67;            // row 0, groups 1..8
                else             f4 = 330 + (k - 75);    // row 33, groups 1..8
                smv[q * (PSZ2 / 4) + f4] = z4;
            }
        }
    }
    // v1: same 336 border words per plane, scalar stores at +1361
    {
        #pragma unroll
        for (int q = 0; q < 4; q++) {
            #pragma unroll
            for (int i = 0; i < 2; i++) {
                int t = tid + i * 256;
                if (t < 336) {
                    int row, col;
                    if (t < 256) { row = 1 + (t >> 3); int c8 = t & 7;
                                   col = (c8 < 4) ? c8 : c8 + 32; }
                    else         { int s = t - 256;
                                   row = (s < 40) ? 0 : 33;
                                   col = (s < 40) ? s : s - 40; }
                    sm[q * PSZ2 + 1361 + row * PW + col] = 0.f;
                }
            }
        }
    }

    // --- leaf word offsets: threads 0..7 decode (parity -> copy select) ---
    if (tid < 8) {
        int idx = __ldg(&leaf_idx[oc * 8 + tid]);
        int ch  = idx / 9;
        int pos = idx - ch * 9;
        int ki  = pos / 3;
        int kj  = pos - ki * 3;
        // element index e = (ki+y)*PW + x + kj + 3 ; parity(e) = parity(kj+1)
        // kj odd  -> e even -> v0 (even base);  kj even -> v1 (base+1361, odd)
        int base = (tid >> 2) * PSZ2 + ((kj & 1) ? 0 : 1361);
        s_off[tid] = base + ki * PW + kj + 3;
    }

    // --- softmax -> 4 affine coefficients, threads 0..3 (gate = tid) -----
    if (tid < 4) {
        const float T0[16]  = {0,0,0,0,0,0,0,0, 1, 1, 1, 1, 1, 1, 1, 1};
        const float TA[16]  = {0,0,1,1,0,0,1,1,-1,-1, 0, 0,-1,-1, 0, 0};
        const float TB[16]  = {0,0,0,0,1,1,1,1,-1,-1,-1,-1, 0, 0, 0, 0};
        const float TAB[16] = {0,1,-1,0,-1,0,-2,-1, 1, 2, 0, 1, 0, 1,-1, 0};

        const float* wp = w + (oc * 7 + tid) * 16;   // weights [C_out, 7, 16]

        float m = wp[0];
        #pragma unroll
        for (int i = 1; i < 16; i++) m = fmaxf(m, wp[i]);

        float e[16];
        float s = 0.f;
        #pragma unroll
        for (int i = 0; i < 16; i++) { e[i] = __expf(wp[i] - m); s += e[i]; }
        float inv = 1.f / s;

        float c0 = 0.f, ca = 0.f, cb = 0.f, cab = 0.f;
        #pragma unroll
        for (int i = 0; i < 16; i++) {
            c0  += e[i] * T0[i];
            ca  += e[i] * TA[i];
            cb  += e[i] * TB[i];
            cab += e[i] * TAB[i];
        }
        s_coef[tid * 4 + 0] = c0 * inv;
        s_coef[tid * 4 + 1] = ca * inv;
        s_coef[tid * 4 + 2] = cb * inv;
        s_coef[tid * 4 + 3] = cab * inv;
    }

    // --- batch 0 ready (1 group still pending) + smem metadata visible ---
    asm volatile("cp.async.wait_group 1;\n");
    __syncthreads();

    // packed coefficients (each lane identical)
    ull K0[4], K1[4], K2[4], K3[4];
    #pragma unroll
    for (int i = 0; i < 4; i++) { K0[i] = pack2(s_coef[i]);      K1[i] = pack2(s_coef[4+i]);
                                  K2[i] = pack2(s_coef[8+i]);    K3[i] = pack2(s_coef[12+i]); }

    // Per-thread pixel pair: y = tid>>4 (0..15), x2 = (tid&15)*2
    const int y   = tid >> 4;
    const int x2  = (tid & 15) * 2;
    const int pb0 = y * PW + x2;                 // even word offset

    const uint32_t smb = (uint32_t)__cvta_generic_to_shared(sm);
    uint32_t A[8];
    #pragma unroll
    for (int i = 0; i < 8; i++) A[i] = smb + 4u * (uint32_t)(s_off[i] + pb0);

    const int tpix = y * 32 + x2;                // output offset within plane

    #pragma unroll
    for (int u = 0; u < NB; u++) {
        if (u == 1) {
            asm volatile("cp.async.wait_group 0;\n");
            __syncthreads();
        }
        float* ob = out + ((size_t)(bg * NB + u) * C_OUT + oc) * (HH * WW) + tpix;

        #pragma unroll
        for (int pr = 0; pr < 2; pr++) {         // rows y and y+16
            // literal byte offset: batch buffer + pair row offset
            const int OFS = u * (BUF * 4) + pr * (16 * PW * 4);

            ull l0, l1, l2, l3, l4, l5, l6, l7;
            if (u == 0 && pr == 0) {
                l0 = lds64<0>(A[0]); l1 = lds64<0>(A[1]);
                l2 = lds64<0>(A[2]); l3 = lds64<0>(A[3]);
                l4 = lds64<0>(A[4]); l5 = lds64<0>(A[5]);
                l6 = lds64<0>(A[6]); l7 = lds64<0>(A[7]);
            } else if (u == 0 && pr == 1) {
                l0 = lds64<16*PW*4>(A[0]); l1 = lds64<16*PW*4>(A[1]);
                l2 = lds64<16*PW*4>(A[2]); l3 = lds64<16*PW*4>(A[3]);
                l4 = lds64<16*PW*4>(A[4]); l5 = lds64<16*PW*4>(A[5]);
                l6 = lds64<16*PW*4>(A[6]); l7 = lds64<16*PW*4>(A[7]);
            } else if (u == 1 && pr == 0) {
                l0 = lds64<BUF*4>(A[0]); l1 = lds64<BUF*4>(A[1]);
                l2 = lds64<BUF*4>(A[2]); l3 = lds64<BUF*4>(A[3]);
                l4 = lds64<BUF*4>(A[4]); l5 = lds64<BUF*4>(A[5]);
                l6 = lds64<BUF*4>(A[6]); l7 = lds64<BUF*4>(A[7]);
            } else {
                l0 = lds64<BUF*4+16*PW*4>(A[0]); l1 = lds64<BUF*4+16*PW*4>(A[1]);
                l2 = lds64<BUF*4+16*PW*4>(A[2]); l3 = lds64<BUF*4+16*PW*4>(A[3]);
                l4 = lds64<BUF*4+16*PW*4>(A[4]); l5 = lds64<BUF*4+16*PW*4>(A[5]);
                l6 = lds64<BUF*4+16*PW*4>(A[6]); l7 = lds64<BUF*4+16*PW*4>(A[7]);
            }
            (void)OFS;

            // level 0: weight rows 0,1,2,3
            ull m0 = gate2(K0, l0, l1);
            ull m1 = gate2(K1, l2, l3);
            ull m2 = gate2(K2, l4, l5);
            ull m3 = gate2(K3, l6, l7);
            // level 1: rows 1,2
            ull n0 = gate2(K1, m0, m1);
            ull n1 = gate2(K2, m2, m3);
            // level 2: row 3
            ull r  = gate2(K3, n0, n1);

            *(ull*)(ob + pr * 512) = r;          // STG.64, two consecutive pixels
        }
    }
}

extern "C" void kernel_launch(void* const* d_in, const int* in_sizes, int n_in,
                              void* d_out, int out_size)
{
    const float* x   = (const float*)d_in[0];          // [16,64,32,32]
    const float* w   = (const float*)d_in[1];          // [128,7,16]
    const int*   idx = (const int*)d_in[2];            // [128,8]
    float*       out = (float*)d_out;                  // [16,128,32,32]

    tree_kernel<<<(BATCH / NB) * C_OUT, 256>>>(x, w, idx, out);
}

// round 7
// speedup vs baseline: 1.2388x; 1.2388x over previous
#include <cuda_runtime.h>
#include <cstdint>

// Problem constants (fixed by the dataset)
#define BATCH   16
#define C_IN    64
#define HH      32
#define WW      32
#define C_OUT   128
#define PH      34          // padded plane height (1 + 32 + 1)
#define PW      40          // padded plane width: 4 left + 32 + 4 right (16B-aligned interior)
#define PLANE   (PH*PW)     // 1360 floats
#define PLANE4  (PLANE/4)   // 340 float4
#define BUF     (2*PLANE)   // one batch = 2 planes = 2720 floats
#define NB      2           // batches per block

// 16B async copy global->shared (LDGSTS.128)
__device__ __forceinline__ void cp16(float* dst_smem, const float* src) {
    uint32_t d = (uint32_t)__cvta_generic_to_shared(dst_smem);
    asm volatile("cp.async.cg.shared.global [%0], [%1], 16;\n" :: "r"(d), "l"(src));
}

// 32-bit shared load with compile-time immediate byte offset
template <int IMM>
__device__ __forceinline__ float lds32(uint32_t addr) {
    float v;
    asm volatile("ld.shared.f32 %0, [%1 + %2];" : "=f"(v) : "r"(addr), "n"(IMM));
    return v;
}

// gate(a,b) = c0 + ca*a + cb*b + cab*a*b, factored to 3 FMAs:
//   fma(fma(cab,b,ca), a, fma(cb,b,c0))
__device__ __forceinline__ float gate3(const float k[4], float a, float b) {
    return fmaf(fmaf(k[3], b, k[1]), a, fmaf(k[2], b, k[0]));
}

// ---------------------------------------------------------------------------
// One block per (oc, batch-pair). NB=2 cp.async double-buffered staging,
// decode/softmax by threads 0..7 into smem, hot loop 8 LDS + 21 FMA + 1 STG
// per pixel with immediate-offset addressing. __launch_bounds__(256,7) caps
// regs at 36 -> 7 blocks/SM -> the whole 1024-block grid fits in ONE wave.
// ---------------------------------------------------------------------------
__global__ void __launch_bounds__(256, 7)
tree_kernel(const float* __restrict__ x,
            const float* __restrict__ w,
            const int*   __restrict__ leaf_idx,
            float*       __restrict__ out)
{
    __shared__ __align__(16) float sm[NB * BUF];   // 21760 B
    __shared__ float s_coef[16];                   // 4 gates x {c0,ca,cb,cab}
    __shared__ int   s_off[8];                     // leaf word offsets
    __shared__ int   s_chan[2];                    // the two source channels

    const int blk = blockIdx.x;          // 0..1023
    const int oc  = blk & (C_OUT - 1);
    const int bg  = blk >> 7;            // 0..7 -> batches 2*bg, 2*bg+1
    const int tid = threadIdx.x;

    // --- decode: threads 0..7 -> leaf offsets + channels ------------------
    if (tid < 8) {
        int idx = __ldg(&leaf_idx[oc * 8 + tid]);
        int ch  = idx / 9;
        int pos = idx - ch * 9;
        int ki  = pos / 3;
        int kj  = pos - ki * 3;
        s_off[tid] = (tid >> 2) * PLANE + ki * PW + kj;
        if ((tid & 3) == 0) s_chan[tid >> 2] = ch;
    }

    // --- softmax -> 4 affine coefficients, threads 0..3 (gate = tid) -----
    // op order: 0, ab, a-ab, a, b-ab, b, s-2ab, s-ab, 1-(s-ab), 1-(s-2ab),
    //           1-b, 1-b+ab, 1-a, 1-a+ab, 1-ab, 1
    if (tid < 4) {
        const float T0[16]  = {0,0,0,0,0,0,0,0, 1, 1, 1, 1, 1, 1, 1, 1};
        const float TA[16]  = {0,0,1,1,0,0,1,1,-1,-1, 0, 0,-1,-1, 0, 0};
        const float TB[16]  = {0,0,0,0,1,1,1,1,-1,-1,-1,-1, 0, 0, 0, 0};
        const float TAB[16] = {0,1,-1,0,-1,0,-2,-1, 1, 2, 0, 1, 0, 1,-1, 0};

        const float* wp = w + (oc * 7 + tid) * 16;   // weights [C_out, 7, 16]

        float m = wp[0];
        #pragma unroll
        for (int i = 1; i < 16; i++) m = fmaxf(m, wp[i]);

        float e[16];
        float s = 0.f;
        #pragma unroll
        for (int i = 0; i < 16; i++) { e[i] = __expf(wp[i] - m); s += e[i]; }
        float inv = 1.f / s;

        float c0 = 0.f, ca = 0.f, cb = 0.f, cab = 0.f;
        #pragma unroll
        for (int i = 0; i < 16; i++) {
            c0  += e[i] * T0[i];
            ca  += e[i] * TA[i];
            cb  += e[i] * TB[i];
            cab += e[i] * TAB[i];
        }
        s_coef[tid * 4 + 0] = c0 * inv;
        s_coef[tid * 4 + 1] = ca * inv;
        s_coef[tid * 4 + 2] = cb * inv;
        s_coef[tid * 4 + 3] = cab * inv;
    }

    // --- zero the border words read by the gather (no divisions) ---------
    // Per plane, 84 float4 slots padded to 128: k<68 -> side col-groups {0,9}
    // of rows 0..33; 68..75 -> row 0 cols 4..35; 76..83 -> row 33 cols 4..35.
    {
        float4 z = make_float4(0.f, 0.f, 0.f, 0.f);
        float4* smv = (float4*)sm;
        #pragma unroll
        for (int i = 0; i < 2; i++) {
            int t = tid + i * 256;       // 0..511 = 4 planes x 128 slots
            int q = t >> 7;              // plane 0..3 (contiguous)
            int k = t & 127;
            if (k < 84) {
                int f4;
                if (k < 68)      f4 = (k >> 1) * 10 + ((k & 1) ? 9 : 0);
                else if (k < 76) f4 = k - 67;            // row 0, groups 1..8
                else             f4 = 330 + (k - 75);    // row 33, groups 1..8
                smv[q * PLANE4 + f4] = z;
            }
        }
    }
    __syncthreads();                     // decode + borders visible

    // --- issue async stages for both batches (one commit group per batch) --
    // Per batch: 2 planes x 32 rows x 8 float4 = 512 copies -> 2 per thread.
    const int chA = s_chan[0], chB = s_chan[1];
    #pragma unroll
    for (int u = 0; u < NB; u++) {
        const float* xb = x + ((size_t)(bg * NB + u) * C_IN) * (HH * WW);
        #pragma unroll
        for (int i = 0; i < 2; i++) {
            int t  = tid + i * 256;      // 0..511
            int p  = t >> 8;             // plane select
            int j  = t & 255;            // r*8 + c4
            int r  = j >> 3;
            int c4 = j & 7;
            const float* src = xb + (p ? chB : chA) * (HH * WW) + j * 4;
            float* dst = sm + u * BUF + p * PLANE + (r + 1) * PW + 4 + c4 * 4;
            cp16(dst, src);
        }
        asm volatile("cp.async.commit_group;\n");
    }

    // --- batch 0 ready (1 group still pending) ----------------------------
    asm volatile("cp.async.wait_group 1;\n");
    __syncthreads();

    // Coefficients to registers (broadcast LDS)
    float k0[4], k1[4], k2[4], k3[4];
    #pragma unroll
    for (int i = 0; i < 4; i++) { k0[i] = s_coef[i];      k1[i] = s_coef[4+i];
                                  k2[i] = s_coef[8+i];    k3[i] = s_coef[12+i]; }

    // Per-thread base pixel: y = tid>>5, x = tid&31 -> padded col x+3
    const int pb0 = (tid >> 5) * PW + (tid & 31) + 3;

    // 8 leaf smem byte-addresses (u/t handled by literal offsets)
    const uint32_t smb = (uint32_t)__cvta_generic_to_shared(sm);
    uint32_t A[8];
    #pragma unroll
    for (int i = 0; i < 8; i++) A[i] = smb + 4u * (uint32_t)(s_off[i] + pb0);

    float* ob = out + ((size_t)(bg * NB) * C_OUT + oc) * (HH * WW) + tid;

    #pragma unroll
    for (int u = 0; u < NB; u++) {
        if (u == 1) {
            asm volatile("cp.async.wait_group 0;\n");
            __syncthreads();
            ob += (size_t)C_OUT * (HH * WW);
        }
        #pragma unroll
        for (int t = 0; t < 4; t++) {
            constexpr int S = 8 * PW * 4;        // byte stride per t step
            const int B = u * (BUF * 4) + t * S; // compile-time after unroll

            float l0, l1, l2, l3, l4, l5, l6, l7;
            switch (B) {                          // all arms constant-folded
              case 0*S:        l0=lds32<0*S>(A[0]); l1=lds32<0*S>(A[1]); l2=lds32<0*S>(A[2]); l3=lds32<0*S>(A[3]); l4=lds32<0*S>(A[4]); l5=lds32<0*S>(A[5]); l6=lds32<0*S>(A[6]); l7=lds32<0*S>(A[7]); break;
              case 1*S:        l0=lds32<1*S>(A[0]); l1=lds32<1*S>(A[1]); l2=lds32<1*S>(A[2]); l3=lds32<1*S>(A[3]); l4=lds32<1*S>(A[4]); l5=lds32<1*S>(A[5]); l6=lds32<1*S>(A[6]); l7=lds32<1*S>(A[7]); break;
              case 2*S:        l0=lds32<2*S>(A[0]); l1=lds32<2*S>(A[1]); l2=lds32<2*S>(A[2]); l3=lds32<2*S>(A[3]); l4=lds32<2*S>(A[4]); l5=lds32<2*S>(A[5]); l6=lds32<2*S>(A[6]); l7=lds32<2*S>(A[7]); break;
              case 3*S:        l0=lds32<3*S>(A[0]); l1=lds32<3*S>(A[1]); l2=lds32<3*S>(A[2]); l3=lds32<3*S>(A[3]); l4=lds32<3*S>(A[4]); l5=lds32<3*S>(A[5]); l6=lds32<3*S>(A[6]); l7=lds32<3*S>(A[7]); break;
              case BUF*4+0*S:  l0=lds32<BUF*4+0*S>(A[0]); l1=lds32<BUF*4+0*S>(A[1]); l2=lds32<BUF*4+0*S>(A[2]); l3=lds32<BUF*4+0*S>(A[3]); l4=lds32<BUF*4+0*S>(A[4]); l5=lds32<BUF*4+0*S>(A[5]); l6=lds32<BUF*4+0*S>(A[6]); l7=lds32<BUF*4+0*S>(A[7]); break;
              case BUF*4+1*S:  l0=lds32<BUF*4+1*S>(A[0]); l1=lds32<BUF*4+1*S>(A[1]); l2=lds32<BUF*4+1*S>(A[2]); l3=lds32<BUF*4+1*S>(A[3]); l4=lds32<BUF*4+1*S>(A[4]); l5=lds32<BUF*4+1*S>(A[5]); l6=lds32<BUF*4+1*S>(A[6]); l7=lds32<BUF*4+1*S>(A[7]); break;
              case BUF*4+2*S:  l0=lds32<BUF*4+2*S>(A[0]); l1=lds32<BUF*4+2*S>(A[1]); l2=lds32<BUF*4+2*S>(A[2]); l3=lds32<BUF*4+2*S>(A[3]); l4=lds32<BUF*4+2*S>(A[4]); l5=lds32<BUF*4+2*S>(A[5]); l6=lds32<BUF*4+2*S>(A[6]); l7=lds32<BUF*4+2*S>(A[7]); break;
              default:         l0=lds32<BUF*4+3*S>(A[0]); l1=lds32<BUF*4+3*S>(A[1]); l2=lds32<BUF*4+3*S>(A[2]); l3=lds32<BUF*4+3*S>(A[3]); l4=lds32<BUF*4+3*S>(A[4]); l5=lds32<BUF*4+3*S>(A[5]); l6=lds32<BUF*4+3*S>(A[6]); l7=lds32<BUF*4+3*S>(A[7]); break;
            }

            // level 0: weight rows 0,1,2,3
            float m0 = gate3(k0, l0, l1);
            float m1 = gate3(k1, l2, l3);
            float m2 = gate3(k2, l4, l5);
            float m3 = gate3(k3, l6, l7);
            // level 1: rows 1,2
            float n0 = gate3(k1, m0, m1);
            float n1 = gate3(k2, m2, m3);
            // level 2: row 3
            float r  = gate3(k3, n0, n1);

            ob[t * 256] = r;
        }
    }
}

extern "C" void kernel_launch(void* const* d_in, const int* in_sizes, int n_in,
                              void* d_out, int out_size)
{
    const float* x   = (const float*)d_in[0];          // [16,64,32,32]
    const float* w   = (const float*)d_in[1];          // [128,7,16]
    const int*   idx = (const int*)d_in[2];            // [128,8]
    float*       out = (float*)d_out;                  // [16,128,32,32]

    tree_kernel<<<(BATCH / NB) * C_OUT, 256>>>(x, w, idx, out);
}